// round 15
// baseline (speedup 1.0000x reference)
#include <cuda_runtime.h>
#include <math.h>

#define NB 8
#define NC 20
#define NROWS 160
#define NP 8732
#define NM 16
#define NQ 4
#define NPQ 2183             // NP/4 exactly
#define THREADS 512
#define THRESH_BITS 0x3F000000   // bits of 0.5f

// ---- global scratch (zero-init at load; all self-restored per launch) ----
__device__ float g_ce[NROWS * NP];
__device__ unsigned long long g_best[NROWS * NM];
__device__ unsigned g_hist[NROWS * 256];
__device__ float g_pl1[NROWS * NQ], g_pcp[NROWS * NQ];
__device__ int   g_pnp[NROWS * NQ];
__device__ int   g_rowcnt[NROWS];
__device__ float g_rconf[NROWS], g_rl1[NROWS], g_rnp[NROWS];
__device__ int   g_counter;

__device__ __forceinline__ float warp_sum(float v) {
#pragma unroll
    for (int o = 16; o; o >>= 1) v += __shfl_down_sync(0xffffffffu, v, o);
    return v;
}
__device__ __forceinline__ unsigned long long warp_max_u64(unsigned long long v) {
#pragma unroll
    for (int o = 16; o; o >>= 1) {
        unsigned long long u = __shfl_down_sync(0xffffffffu, v, o);
        v = (u > v) ? u : v;
    }
    return v;
}
__device__ __forceinline__ float ce_from_scores(float2 sc, int cls) {
    float mx = fmaxf(sc.x, sc.y);
    return mx + __logf(1.f + __expf(-fabsf(sc.x - sc.y))) - (cls ? sc.y : sc.x);
}
__device__ __forceinline__ float l1_term(float4 b, float4 pr, float4 pl) {
    float cx = (b.x + b.z) * 0.5f, cy = (b.y + b.w) * 0.5f;
    float w  = b.z - b.x,          h  = b.w - b.y;
    float gx = __fdividef((cx - pr.x) * 10.f, pr.z);
    float gy = __fdividef((cy - pr.y) * 10.f, pr.w);
    float gw = __logf(__fdividef(w, pr.z)) * 5.f;
    float gh = __logf(__fdividef(h, pr.w)) * 5.f;
    return fabsf(pl.x - gx) + fabsf(pl.y - gy) + fabsf(pl.z - gw) + fabsf(pl.w - gh);
}

// warp-parallel suffix-scan selection over 256 bins
__device__ __forceinline__ void select_scan(unsigned* s_hist, unsigned* s_pref, int* s_kk,
                                            unsigned pref, int shift, int lane, int tid)
{
    if (tid < 32) {
        int kk = *s_kk;
        __syncwarp();
        unsigned h[8]; unsigned lsum = 0;
        const int base = (31 - lane) * 8;
#pragma unroll
        for (int i = 0; i < 8; i++) { h[i] = s_hist[base + i]; lsum += h[i]; }
        unsigned incl = lsum;
#pragma unroll
        for (int off = 1; off < 32; off <<= 1) {
            unsigned v = __shfl_up_sync(0xffffffffu, incl, off);
            if (lane >= off) incl += v;
        }
        unsigned excl = incl - lsum;
        if (excl < (unsigned)kk && incl >= (unsigned)kk) {
            unsigned cum = excl;
#pragma unroll
            for (int i = 7; i >= 0; i--) {
                unsigned cnt = h[i];
                if (cum + cnt >= (unsigned)kk) {
                    *s_pref = pref | ((unsigned)(base + i) << shift);
                    *s_kk   = kk - (int)cum;
                    break;
                }
                cum += cnt;
            }
        }
    }
}

__global__ __launch_bounds__(THREADS, 2) void mb_quarter_kernel(
    const float* __restrict__ ploc, const float* __restrict__ pscore,
    const float* __restrict__ boxes, const int* __restrict__ labels,
    const float* __restrict__ priors, float* __restrict__ out)
{
    __shared__ int            s_key[NP];     // worker: packed (iou&~0xF)|m for own quarter
                                             // merger: full-row ce bits
    __shared__ float4         s_bx4[NM];
    __shared__ float          s_area[NM];
    __shared__ int            s_lab[NM];
    __shared__ unsigned long long s_best[NM];
    __shared__ unsigned int   s_hist[256];
    __shared__ float          s_dl1[NM], s_dcp[NM], s_dnp[NM];
    __shared__ float          s_sumgt, s_conf, s_l1t, s_npf;
    __shared__ int            s_npos, s_kk, s_fin, s_merge;
    __shared__ unsigned int   s_pref;
    __shared__ float          s_wl1[16], s_wcp[16];
    __shared__ int            s_wnp[16];

    const int bid  = blockIdx.x;
    const int row  = bid >> 2, quad = bid & 3;
    const int tid  = threadIdx.x;
    const int lane = tid & 31, wid = tid >> 5;
    const int p0   = quad * NPQ;
    const float4* __restrict__ prior4 = (const float4*)priors;
    const float2* __restrict__ sc2 = (const float2*)pscore + (size_t)row * NP;
    const float4* __restrict__ pl4 = (const float4*)ploc   + (size_t)row * NP;

    if (tid < NM) {
        const float* b = boxes + ((size_t)row * NM + tid) * 4;
        float4 v = make_float4(b[0], b[1], b[2], b[3]);
        s_bx4[tid]  = v;
        s_area[tid] = (v.z - v.x) * (v.w - v.y);
        s_lab[tid]  = labels[(size_t)row * NM + tid];
        s_best[tid] = 0ull;
        s_dl1[tid] = 0.f; s_dcp[tid] = 0.f; s_dnp[tid] = 0.f;
    }
    if (tid < 256) s_hist[tid] = 0u;
    if (tid == 0) { s_sumgt = 0.f; s_fin = 0; }
    __syncthreads();

    // ---- pass 1: IoU over my quarter (2 chunks of 8 boxes), packed argmax ----
#pragma unroll 1
    for (int ch = 0; ch < 2; ch++) {
        const int mbase = ch * 8;
        float bx1[8], by1[8], bx2[8], by2[8], ba[8];
#pragma unroll
        for (int i = 0; i < 8; i++) {
            float4 b = s_bx4[mbase + i];
            bx1[i] = b.x; by1[i] = b.y; bx2[i] = b.z; by2[i] = b.w;
            ba[i] = s_area[mbase + i];
        }
        unsigned bbest[8] = {0u,0u,0u,0u,0u,0u,0u,0u};
        int it = 0;
        for (int li = tid; li < NPQ; li += THREADS, it++) {
            float4 pr = prior4[p0 + li];
            float hw = pr.z * 0.5f, hh = pr.w * 0.5f;
            float px1 = pr.x - hw, py1 = pr.y - hh;
            float px2 = pr.x + hw, py2 = pr.y + hh;
            float parea = (px2 - px1) * (py2 - py1);
            int best = (ch == 0) ? 0 : s_key[li];
#pragma unroll
            for (int i = 0; i < 8; i++) {
                float iw = fminf(bx2[i], px2) - fmaxf(bx1[i], px1);
                float ih = fminf(by2[i], py2) - fmaxf(by1[i], py1);
                iw = fmaxf(iw, 0.f); ih = fmaxf(ih, 0.f);
                float inter = iw * ih;
                int ib = __float_as_int(__fdividef(inter, ba[i] + parea - inter));
                best = max(best, (ib & 0xFFFFFFF0) | (mbase + i));   // per-prior argmax
                unsigned kb = ((unsigned)ib & 0xFFFFFFE0u) | (unsigned)(31 - it);
                bbest[i] = kb > bbest[i] ? kb : bbest[i];            // per-box best
            }
            s_key[li] = best;
        }
#pragma unroll
        for (int i = 0; i < 8; i++) {
            int itw = 31 - (int)(bbest[i] & 31u);
            int pw  = p0 + itw * THREADS + tid;
            if (pw >= p0 + NPQ) pw = p0 + NPQ - 1;   // only reachable with value bits 0
            unsigned long long key =
                ((unsigned long long)(bbest[i] & 0xFFFFFFE0u) << 32) |
                (unsigned)(NP - 1 - pw);             // tie -> lowest global p
            key = warp_max_u64(key);
            if (lane == 0) atomicMax(&s_best[mbase + i], key);
        }
    }
    __syncthreads();
    if (tid < NM) atomicMax(&g_best[row * NM + tid], s_best[tid]);

    // ---- pass 2: provisional CE/L1/npos over my quarter + top-byte histogram ----
    {
        float l1_acc = 0.f, cp_acc = 0.f, np_acc = 0.f;
        for (int li = tid; li < NPQ; li += THREADS) {
            int p = p0 + li;
            int key = s_key[li];
            int m = key & 15;
            int cls = (key >= THRESH_BITS) ? s_lab[m] : 0;
            float2 sc = sc2[p];
            float ce = ce_from_scores(sc, cls);
            if (cls != 0) {
                np_acc += 1.f;
                cp_acc += ce;
                l1_acc += l1_term(s_bx4[m], prior4[p], pl4[p]);
                ce = 0.f;
            }
            g_ce[(size_t)row * NP + p] = ce;
            unsigned mask = __activemask();
            unsigned bin  = __float_as_uint(ce) >> 24;
            unsigned peers = __match_any_sync(mask, bin);
            if ((int)(__ffs(peers) - 1) == lane)
                atomicAdd(&s_hist[bin], (unsigned)__popc(peers));
        }
        l1_acc = warp_sum(l1_acc); cp_acc = warp_sum(cp_acc); np_acc = warp_sum(np_acc);
        if (lane == 0) { s_wl1[wid] = l1_acc; s_wcp[wid] = cp_acc; s_wnp[wid] = (int)np_acc; }
    }
    __syncthreads();
    if (tid == 0) {
        float a = 0.f, b = 0.f; int c = 0;
        for (int w = 0; w < 16; w++) { a += s_wl1[w]; b += s_wcp[w]; c += s_wnp[w]; }
        g_pl1[row * NQ + quad] = a;
        g_pcp[row * NQ + quad] = b;
        g_pnp[row * NQ + quad] = c;
    }
    if (tid < 256 && s_hist[tid]) atomicAdd(&g_hist[row * 256 + tid], s_hist[tid]);
    __syncthreads();
    if (tid == 0) {
        __threadfence();
        int old = atomicAdd(&g_rowcnt[row], 1);
        s_merge = (old == NQ - 1);
    }
    __syncthreads();
    if (!s_merge) return;

    // ================= MERGER (last finisher; no spinning) =================
    __threadfence();
    if (tid == 0) g_rowcnt[row] = 0;   // restore for replay
    if (tid < 256) {
        unsigned h = ((volatile unsigned*)g_hist)[row * 256 + tid];
        g_hist[row * 256 + tid] = 0u;  // restore
        s_hist[tid] = h;
    }
    // full CE row -> smem (L2-hot)
    {
        const float4* gce4 = (const float4*)(g_ce + (size_t)row * NP);
        float4* sce4 = (float4*)s_key;
        for (int i = tid; i < NP / 4; i += THREADS) sce4[i] = __ldcg(&gce4[i]);
    }
    if (tid == 0) {
        volatile float* vl1 = g_pl1; volatile float* vcp = g_pcp; volatile int* vnp = g_pnp;
        float a = 0.f, b = 0.f; int c = 0;
#pragma unroll
        for (int q = 0; q < NQ; q++) {
            a += vl1[row * NQ + q]; b += vcp[row * NQ + q]; c += vnp[row * NQ + q];
        }
        s_l1t = a; s_conf = b; s_npf = (float)c;
    }
    __syncthreads();
    float* s_ce = (float*)s_key;

    // ---- forced-match fix-up (16 lanes; last-write-wins => owner = highest m) ----
    if (tid < NM) {
        unsigned long long key = ((volatile unsigned long long*)g_best)[row * NM + tid];
        g_best[row * NM + tid] = 0ull;    // restore
        int pp = NP - 1 - (int)(unsigned)(key & 0xFFFFFFFFull);
        unsigned peers = __match_any_sync(0x0000FFFFu, pp);
        if ((31 - __clz(peers)) == tid) {
            float4 pr = prior4[pp];
            float hw = pr.z * 0.5f, hh = pr.w * 0.5f;
            float px1 = pr.x - hw, py1 = pr.y - hh;
            float px2 = pr.x + hw, py2 = pr.y + hh;
            float parea = (px2 - px1) * (py2 - py1);
            int best = 0;
#pragma unroll
            for (int m = 0; m < NM; m++) {
                float4 b = s_bx4[m];
                float iw = fminf(b.z, px2) - fmaxf(b.x, px1);
                float ih = fminf(b.w, py2) - fmaxf(b.y, py1);
                iw = fmaxf(iw, 0.f); ih = fmaxf(ih, 0.f);
                float inter = iw * ih;
                int ib = __float_as_int(__fdividef(inter, s_area[m] + parea - inter));
                best = max(best, (ib & 0xFFFFFFF0) | m);   // identical to worker
            }
            int bm = best & 15;
            int cls_old = (best >= THRESH_BITS) ? s_lab[bm] : 0;
            float2 sc = sc2[pp];
            float4 pl = pl4[pp];
            float ce_old = ce_from_scores(sc, cls_old);
            float dl1 = 0.f, dcp = 0.f, dnp = 0.f;
            unsigned ob;
            if (cls_old) { dnp -= 1.f; dcp -= ce_old; dl1 -= l1_term(s_bx4[bm], pr, pl); ob = 0u; }
            else ob = __float_as_uint(ce_old) >> 24;
            int cls_new = s_lab[tid];
            float ce_new = ce_from_scores(sc, cls_new);
            float cenew;
            if (cls_new) { dnp += 1.f; dcp += ce_new; dl1 += l1_term(s_bx4[tid], pr, pl); cenew = 0.f; }
            else cenew = ce_new;
            unsigned nb = __float_as_uint(cenew) >> 24;
            s_ce[pp] = cenew;
            if (ob != nb) { atomicSub(&s_hist[ob], 1u); atomicAdd(&s_hist[nb], 1u); }
            s_dl1[tid] = dl1; s_dcp[tid] = dcp; s_dnp[tid] = dnp;
        }
    }
    __syncthreads();
    if (tid == 0) {
        for (int m = 0; m < NM; m++) { s_l1t += s_dl1[m]; s_conf += s_dcp[m]; s_npf += s_dnp[m]; }
        s_npos = (int)s_npf;
    }
    __syncthreads();

    const int npos = s_npos;
    int K = 3 * npos; if (K > NP) K = NP;
    float conf_hard = 0.f;

    if (K > 0) {
        if (tid == 0) { s_pref = 0u; s_kk = K; }
        __syncthreads();
        select_scan(s_hist, &s_pref, &s_kk, 0u, 24, lane, tid);
        __syncthreads();
#pragma unroll 1
        for (int pass = 2; pass >= 1; pass--) {
            const int shift = pass * 8;
            if (tid < 256) s_hist[tid] = 0u;
            __syncthreads();
            const unsigned pref   = s_pref;
            const unsigned maskHi = 0xFFFFFFFFu << (shift + 8);
            for (int p1 = 0; p1 < NP; p1 += THREADS) {
                int p = p1 + tid;
                bool pred = false; int bin = 0;
                if (p < NP) {
                    unsigned keyb = __float_as_uint(s_ce[p]);
                    pred = ((keyb & maskHi) == pref);
                    bin  = (keyb >> shift) & 0xFF;
                }
                unsigned act = __ballot_sync(0xffffffffu, pred);
                if (pred) {
                    unsigned peers = __match_any_sync(act, bin);
                    if ((__ffs(peers) - 1) == lane)
                        atomicAdd(&s_hist[bin], (unsigned)__popc(peers));
                }
            }
            __syncthreads();
            select_scan(s_hist, &s_pref, &s_kk, pref, shift, lane, tid);
            __syncthreads();
        }
        // T = top-24-bit threshold; s_kk ties counted at T (error <= kk*T*2^-15)
        const unsigned T = s_pref;
        float sum_gt = 0.f;
        for (int p = tid; p < NP; p += THREADS) {
            float v = s_ce[p];
            if ((__float_as_uint(v) & 0xFFFFFF00u) > T) sum_gt += v;
        }
        sum_gt = warp_sum(sum_gt);
        if (lane == 0) atomicAdd(&s_sumgt, sum_gt);
        __syncthreads();
        if (tid == 0) conf_hard = s_sumgt + (float)s_kk * __uint_as_float(T);
    }

    // ---- row outputs + last-merger finalize ----
    if (tid == 0) {
        g_rconf[row] = s_conf + conf_hard;
        g_rl1[row]   = s_l1t;
        g_rnp[row]   = (float)npos;
        __threadfence();
        int t = atomicAdd(&g_counter, 1);
        s_fin = (t == NROWS - 1);
    }
    __syncthreads();
    if (s_fin && tid < 32) {
        __threadfence();
        float v = 0.f;
        if (tid < NC) {
            volatile float* vc = g_rconf;
            volatile float* vl = g_rl1;
            volatile float* vn = g_rnp;
            float conf = 0.f, l1 = 0.f, np = 0.f;
#pragma unroll
            for (int n = 0; n < NB; n++) {
                int r = n * NC + tid;
                conf += vc[r]; l1 += vl[r]; np += vn[r];
            }
            if (np > 0.f)
                v = (conf + l1 / fmaxf(np * 4.f, 1.f)) / fmaxf(np, 1.f);
        }
        v = warp_sum(v);
        if (tid == 0) { out[0] = v / (float)NC; g_counter = 0; }
    }
}

extern "C" void kernel_launch(void* const* d_in, const int* in_sizes, int n_in,
                              void* d_out, int out_size) {
    const float* ploc   = (const float*)d_in[0];
    const float* pscore = (const float*)d_in[1];
    const float* boxes  = (const float*)d_in[2];
    const int*   labels = (const int*)d_in[3];
    const float* priors = (const float*)d_in[4];
    float* out = (float*)d_out;

    mb_quarter_kernel<<<NROWS * NQ, THREADS>>>(ploc, pscore, boxes, labels, priors, out);
}

// round 16
// speedup vs baseline: 1.0905x; 1.0905x over previous
#include <cuda_runtime.h>
#include <math.h>

#define NB 8
#define NC 20
#define NROWS 160
#define NP 8732
#define NM 16
#define THREADS 512
#define THRESH_BITS 0x3F000000   // bits of 0.5f
#define NPH0 4368            // half-0 prior count (float4-aligned)

// ---- global scratch (zero-init at load; all self-restored per launch) ----
__device__ float g_ce[NROWS * NP];
__device__ unsigned long long g_best[NROWS * NM];
__device__ unsigned g_hist[NROWS * 256];
__device__ float g_pl1[NROWS * 2], g_pcp[NROWS * 2];
__device__ int   g_pnp[NROWS * 2];
__device__ int   g_rowcnt[NROWS];
__device__ float g_rconf[NROWS], g_rl1[NROWS], g_rnp[NROWS];
__device__ int   g_counter;

__device__ __forceinline__ float warp_sum(float v) {
#pragma unroll
    for (int o = 16; o; o >>= 1) v += __shfl_down_sync(0xffffffffu, v, o);
    return v;
}
__device__ __forceinline__ unsigned long long warp_max_u64(unsigned long long v) {
#pragma unroll
    for (int o = 16; o; o >>= 1) {
        unsigned long long u = __shfl_down_sync(0xffffffffu, v, o);
        v = (u > v) ? u : v;
    }
    return v;
}
__device__ __forceinline__ float ce_from_scores(float2 sc, int cls) {
    float mx = fmaxf(sc.x, sc.y);
    return mx + __logf(1.f + __expf(-fabsf(sc.x - sc.y))) - (cls ? sc.y : sc.x);
}
__device__ __forceinline__ float l1_term(float4 b, float4 pr, float4 pl) {
    float cx = (b.x + b.z) * 0.5f, cy = (b.y + b.w) * 0.5f;
    float w  = b.z - b.x,          h  = b.w - b.y;
    float gx = __fdividef((cx - pr.x) * 10.f, pr.z);
    float gy = __fdividef((cy - pr.y) * 10.f, pr.w);
    float gw = __logf(__fdividef(w, pr.z)) * 5.f;
    float gh = __logf(__fdividef(h, pr.w)) * 5.f;
    return fabsf(pl.x - gx) + fabsf(pl.y - gy) + fabsf(pl.z - gw) + fabsf(pl.w - gh);
}

// warp-parallel suffix-scan selection over 256 bins
__device__ __forceinline__ void select_scan(unsigned* s_hist, unsigned* s_pref, int* s_kk,
                                            unsigned pref, int shift, int lane, int tid)
{
    if (tid < 32) {
        int kk = *s_kk;
        __syncwarp();
        unsigned h[8]; unsigned lsum = 0;
        const int base = (31 - lane) * 8;
#pragma unroll
        for (int i = 0; i < 8; i++) { h[i] = s_hist[base + i]; lsum += h[i]; }
        unsigned incl = lsum;
#pragma unroll
        for (int off = 1; off < 32; off <<= 1) {
            unsigned v = __shfl_up_sync(0xffffffffu, incl, off);
            if (lane >= off) incl += v;
        }
        unsigned excl = incl - lsum;
        if (excl < (unsigned)kk && incl >= (unsigned)kk) {
            unsigned cum = excl;
#pragma unroll
            for (int i = 7; i >= 0; i--) {
                unsigned cnt = h[i];
                if (cum + cnt >= (unsigned)kk) {
                    *s_pref = pref | ((unsigned)(base + i) << shift);
                    *s_kk   = kk - (int)cum;
                    break;
                }
                cum += cnt;
            }
        }
    }
}

__global__ __launch_bounds__(THREADS, 2) void mb_half_kernel(
    const float* __restrict__ ploc, const float* __restrict__ pscore,
    const float* __restrict__ boxes, const int* __restrict__ labels,
    const float* __restrict__ priors, float* __restrict__ out)
{
    __shared__ int            s_key[NP];    // worker: packed (iou&~0xF)|m; merger: ce bits
    __shared__ float4         s_bx4[NM];
    __shared__ float          s_area[NM];
    __shared__ int            s_lab[NM];
    __shared__ unsigned long long s_best[NM];
    __shared__ unsigned int   s_hist[256];
    __shared__ float          s_dl1[NM], s_dcp[NM], s_dnp[NM];
    __shared__ float          s_sumgt, s_conf, s_l1t, s_npf;
    __shared__ int            s_npos, s_kk, s_fin, s_merge;
    __shared__ unsigned int   s_pref;
    __shared__ float          s_wl1[16], s_wcp[16];
    __shared__ int            s_wnp[16];

    const int bid  = blockIdx.x;
    const int row  = bid >> 1, half = bid & 1;
    const int tid  = threadIdx.x;
    const int lane = tid & 31, wid = tid >> 5;
    const int p0   = half ? NPH0 : 0;
    const int pend = half ? NP : NPH0;
    const float4* __restrict__ prior4 = (const float4*)priors;
    const float2* __restrict__ sc2 = (const float2*)pscore + (size_t)row * NP;
    const float4* __restrict__ pl4 = (const float4*)ploc   + (size_t)row * NP;

    if (tid < NM) {
        const float* b = boxes + ((size_t)row * NM + tid) * 4;
        float4 v = make_float4(b[0], b[1], b[2], b[3]);
        s_bx4[tid]  = v;
        s_area[tid] = (v.z - v.x) * (v.w - v.y);
        s_lab[tid]  = labels[(size_t)row * NM + tid];
        s_best[tid] = 0ull;
        s_dl1[tid] = 0.f; s_dcp[tid] = 0.f; s_dnp[tid] = 0.f;
    }
    if (tid < 256) s_hist[tid] = 0u;
    if (tid == 0) { s_sumgt = 0.f; s_fin = 0; }
    __syncthreads();

    // ---- pass 1: IoU over my half (2 chunks of 8 boxes), packed argmax ----
#pragma unroll 1
    for (int ch = 0; ch < 2; ch++) {
        const int mbase = ch * 8;
        float bx1[8], by1[8], bx2[8], by2[8], ba[8];
#pragma unroll
        for (int i = 0; i < 8; i++) {
            float4 b = s_bx4[mbase + i];
            bx1[i] = b.x; by1[i] = b.y; bx2[i] = b.z; by2[i] = b.w;
            ba[i] = s_area[mbase + i];
        }
        unsigned bbest[8] = {0u,0u,0u,0u,0u,0u,0u,0u};
        int it = 0;
        for (int p = p0 + tid; p < pend; p += THREADS, it++) {
            float4 pr = prior4[p];
            float hw = pr.z * 0.5f, hh = pr.w * 0.5f;
            float px1 = pr.x - hw, py1 = pr.y - hh;
            float px2 = pr.x + hw, py2 = pr.y + hh;
            float parea = pr.z * pr.w;
            int best = (ch == 0) ? 0 : s_key[p];
#pragma unroll
            for (int i = 0; i < 8; i++) {
                float iw = fminf(bx2[i], px2) - fmaxf(bx1[i], px1);
                float ih = fminf(by2[i], py2) - fmaxf(by1[i], py1);
                iw = fmaxf(iw, 0.f); ih = fmaxf(ih, 0.f);
                float inter = iw * ih;
                int ib = __float_as_int(__fdividef(inter, ba[i] + parea - inter));
                best = max(best, (ib & 0xFFFFFFF0) | (mbase + i));   // per-prior argmax
                unsigned kb = ((unsigned)ib & 0xFFFFFFE0u) | (unsigned)(31 - it);
                bbest[i] = kb > bbest[i] ? kb : bbest[i];            // per-box best
            }
            s_key[p] = best;
        }
#pragma unroll
        for (int i = 0; i < 8; i++) {
            int itw = 31 - (int)(bbest[i] & 31u);
            int pw  = p0 + itw * THREADS + tid;
            if (pw >= pend) pw = pend - 1;    // only reachable with value bits 0
            unsigned long long key =
                ((unsigned long long)(bbest[i] & 0xFFFFFFE0u) << 32) |
                (unsigned)(NP - 1 - pw);      // tie -> lowest global p
            key = warp_max_u64(key);
            if (lane == 0) atomicMax(&s_best[mbase + i], key);
        }
    }
    __syncthreads();
    if (tid < NM) atomicMax(&g_best[row * NM + tid], s_best[tid]);

    // ---- pass 2: provisional CE/L1/npos over my half + top-byte histogram ----
    {
        float l1_acc = 0.f, cp_acc = 0.f, np_acc = 0.f;
        for (int p = p0 + tid; p < pend; p += THREADS) {
            int key = s_key[p];
            int m = key & 15;
            int cls = (key >= THRESH_BITS) ? s_lab[m] : 0;
            float2 sc = sc2[p];
            float ce = ce_from_scores(sc, cls);
            if (cls != 0) {
                np_acc += 1.f;
                cp_acc += ce;
                l1_acc += l1_term(s_bx4[m], prior4[p], pl4[p]);
                ce = 0.f;
            }
            g_ce[(size_t)row * NP + p] = ce;
            unsigned mask = __activemask();
            unsigned bin  = __float_as_uint(ce) >> 24;
            unsigned peers = __match_any_sync(mask, bin);
            if ((int)(__ffs(peers) - 1) == lane)
                atomicAdd(&s_hist[bin], (unsigned)__popc(peers));
        }
        l1_acc = warp_sum(l1_acc); cp_acc = warp_sum(cp_acc); np_acc = warp_sum(np_acc);
        if (lane == 0) { s_wl1[wid] = l1_acc; s_wcp[wid] = cp_acc; s_wnp[wid] = (int)np_acc; }
    }
    __syncthreads();
    if (tid == 0) {
        float a = 0.f, b = 0.f; int c = 0;
        for (int w = 0; w < 16; w++) { a += s_wl1[w]; b += s_wcp[w]; c += s_wnp[w]; }
        g_pl1[row * 2 + half] = a;
        g_pcp[row * 2 + half] = b;
        g_pnp[row * 2 + half] = c;
    }
    if (tid < 256 && s_hist[tid]) atomicAdd(&g_hist[row * 256 + tid], s_hist[tid]);
    __syncthreads();
    if (tid == 0) {
        __threadfence();
        int old = atomicAdd(&g_rowcnt[row], 1);
        s_merge = (old == 1);
    }
    __syncthreads();
    if (!s_merge) return;

    // ================= MERGER (second finisher; no spinning) =================
    __threadfence();
    if (tid == 0) g_rowcnt[row] = 0;   // restore for replay
    if (tid < 256) {
        unsigned h = ((volatile unsigned*)g_hist)[row * 256 + tid];
        g_hist[row * 256 + tid] = 0u;  // restore
        s_hist[tid] = h;
    }
    // full CE row -> smem (L2-hot)
    {
        const float4* gce4 = (const float4*)(g_ce + (size_t)row * NP);
        float4* sce4 = (float4*)s_key;
        for (int i = tid; i < NP / 4; i += THREADS) sce4[i] = __ldcg(&gce4[i]);
    }
    if (tid == 0) {
        volatile float* vl1 = g_pl1; volatile float* vcp = g_pcp; volatile int* vnp = g_pnp;
        s_l1t  = vl1[row * 2] + vl1[row * 2 + 1];
        s_conf = vcp[row * 2] + vcp[row * 2 + 1];
        s_npf  = (float)(vnp[row * 2] + vnp[row * 2 + 1]);
    }
    __syncthreads();
    float* s_ce = (float*)s_key;

    // ---- forced-match fix-up (16 lanes; last-write-wins => owner = highest m) ----
    if (tid < NM) {
        unsigned long long key = ((volatile unsigned long long*)g_best)[row * NM + tid];
        g_best[row * NM + tid] = 0ull;    // restore
        int pp = NP - 1 - (int)(unsigned)(key & 0xFFFFFFFFull);
        unsigned peers = __match_any_sync(0x0000FFFFu, pp);
        if ((31 - __clz(peers)) == tid) {
            float4 pr = prior4[pp];
            float hw = pr.z * 0.5f, hh = pr.w * 0.5f;
            float px1 = pr.x - hw, py1 = pr.y - hh;
            float px2 = pr.x + hw, py2 = pr.y + hh;
            float parea = pr.z * pr.w;
            int best = 0;
#pragma unroll
            for (int m = 0; m < NM; m++) {
                float4 b = s_bx4[m];
                float iw = fminf(b.z, px2) - fmaxf(b.x, px1);
                float ih = fminf(b.w, py2) - fmaxf(b.y, py1);
                iw = fmaxf(iw, 0.f); ih = fmaxf(ih, 0.f);
                float inter = iw * ih;
                int ib = __float_as_int(__fdividef(inter, s_area[m] + parea - inter));
                best = max(best, (ib & 0xFFFFFFF0) | m);   // identical to worker
            }
            int bm = best & 15;
            int cls_old = (best >= THRESH_BITS) ? s_lab[bm] : 0;
            float2 sc = sc2[pp];
            float4 pl = pl4[pp];
            float ce_old = ce_from_scores(sc, cls_old);
            float dl1 = 0.f, dcp = 0.f, dnp = 0.f;
            unsigned ob;
            if (cls_old) { dnp -= 1.f; dcp -= ce_old; dl1 -= l1_term(s_bx4[bm], pr, pl); ob = 0u; }
            else ob = __float_as_uint(ce_old) >> 24;
            int cls_new = s_lab[tid];
            float ce_new = ce_from_scores(sc, cls_new);
            float cenew;
            if (cls_new) { dnp += 1.f; dcp += ce_new; dl1 += l1_term(s_bx4[tid], pr, pl); cenew = 0.f; }
            else cenew = ce_new;
            unsigned nb = __float_as_uint(cenew) >> 24;
            s_ce[pp] = cenew;
            if (ob != nb) { atomicSub(&s_hist[ob], 1u); atomicAdd(&s_hist[nb], 1u); }
            s_dl1[tid] = dl1; s_dcp[tid] = dcp; s_dnp[tid] = dnp;
        }
    }
    __syncthreads();
    if (tid == 0) {
        for (int m = 0; m < NM; m++) { s_l1t += s_dl1[m]; s_conf += s_dcp[m]; s_npf += s_dnp[m]; }
        s_npos = (int)s_npf;
    }
    __syncthreads();

    const int npos = s_npos;
    int K = 3 * npos; if (K > NP) K = NP;
    float conf_hard = 0.f;

    if (K > 0) {
        if (tid == 0) { s_pref = 0u; s_kk = K; }
        __syncthreads();
        select_scan(s_hist, &s_pref, &s_kk, 0u, 24, lane, tid);
        __syncthreads();
#pragma unroll 1
        for (int pass = 2; pass >= 1; pass--) {
            const int shift = pass * 8;
            if (tid < 256) s_hist[tid] = 0u;
            __syncthreads();
            const unsigned pref   = s_pref;
            const unsigned maskHi = 0xFFFFFFFFu << (shift + 8);
            for (int p1 = 0; p1 < NP; p1 += THREADS) {
                int p = p1 + tid;
                bool pred = false; int bin = 0;
                if (p < NP) {
                    unsigned keyb = __float_as_uint(s_ce[p]);
                    pred = ((keyb & maskHi) == pref);
                    bin  = (keyb >> shift) & 0xFF;
                }
                unsigned act = __ballot_sync(0xffffffffu, pred);
                if (pred) {
                    unsigned peers = __match_any_sync(act, bin);
                    if ((__ffs(peers) - 1) == lane)
                        atomicAdd(&s_hist[bin], (unsigned)__popc(peers));
                }
            }
            __syncthreads();
            select_scan(s_hist, &s_pref, &s_kk, pref, shift, lane, tid);
            __syncthreads();
        }
        // T = top-24-bit threshold; s_kk ties counted at T (error <= kk*T*2^-15)
        const unsigned T = s_pref;
        float sum_gt = 0.f;
        for (int p = tid; p < NP; p += THREADS) {
            float v = s_ce[p];
            if ((__float_as_uint(v) & 0xFFFFFF00u) > T) sum_gt += v;
        }
        sum_gt = warp_sum(sum_gt);
        if (lane == 0) atomicAdd(&s_sumgt, sum_gt);
        __syncthreads();
        if (tid == 0) conf_hard = s_sumgt + (float)s_kk * __uint_as_float(T);
    }

    // ---- row outputs + last-merger finalize ----
    if (tid == 0) {
        g_rconf[row] = s_conf + conf_hard;
        g_rl1[row]   = s_l1t;
        g_rnp[row]   = (float)npos;
        __threadfence();
        int t = atomicAdd(&g_counter, 1);
        s_fin = (t == NROWS - 1);
    }
    __syncthreads();
    if (s_fin && tid < 32) {
        __threadfence();
        float v = 0.f;
        if (tid < NC) {
            volatile float* vc = g_rconf;
            volatile float* vl = g_rl1;
            volatile float* vn = g_rnp;
            float conf = 0.f, l1 = 0.f, np = 0.f;
#pragma unroll
            for (int n = 0; n < NB; n++) {
                int r = n * NC + tid;
                conf += vc[r]; l1 += vl[r]; np += vn[r];
            }
            if (np > 0.f)
                v = (conf + l1 / fmaxf(np * 4.f, 1.f)) / fmaxf(np, 1.f);
        }
        v = warp_sum(v);
        if (tid == 0) { out[0] = v / (float)NC; g_counter = 0; }
    }
}

extern "C" void kernel_launch(void* const* d_in, const int* in_sizes, int n_in,
                              void* d_out, int out_size) {
    const float* ploc   = (const float*)d_in[0];
    const float* pscore = (const float*)d_in[1];
    const float* boxes  = (const float*)d_in[2];
    const int*   labels = (const int*)d_in[3];
    const float* priors = (const float*)d_in[4];
    float* out = (float*)d_out;

    mb_half_kernel<<<NROWS * 2, THREADS>>>(ploc, pscore, boxes, labels, priors, out);
}